// round 1
// baseline (speedup 1.0000x reference)
#include <cuda_runtime.h>
#include <cuda_bf16.h>
#include <cstdint>

// ---------------- problem constants ----------------
#define LQ     11          // tokens per team
#define DMODEL 32
#define NHEAD  4
#define HDIM   8
#define VOCAB  10000
#define NPOS   16
#define PEDIM  16
#define RSQRT8 0.35355339059327373f

#define WPB 4              // warps (=batches) per block

// ---------------- device scratch (no allocations allowed) ----------------
// Fused player tables: row p has 96 floats = [q_role | k_role | v_role]
//   TH (home tokens): [ Wq(h2a)  | Wk(a2h) | Wv(a2h) ] applied to emb half
//   TA (away tokens): [ Wq(a2h)  | Wk(h2a) | Wv(h2a) ]
// q columns pre-scaled by 1/sqrt(8) (bias too, folded into pos tables).
__device__ float g_TH[VOCAB * 96];
__device__ float g_TA[VOCAB * 96];
__device__ float g_PH[NPOS * 96];
__device__ float g_PA[NPOS * 96];
// Epilogue fused weights: wpack[j][c] = {Wh_out[c][j], Wa_out[c][j], Gh[c][j], Ga[c][j]}
__device__ float4 g_wpack[32 * 32];
__device__ float4 g_cvec[32];   // {h2a_out_b, a2h_out_b, fused gate const, 0}

// ---------------- precompute kernels ----------------

// Player tables: thread computes 4 consecutive channels of one row of one table.
__global__ void build_player_tables(const float* __restrict__ emb,
                                    const float* __restrict__ h2a_w,
                                    const float* __restrict__ a2h_w) {
    int idx = blockIdx.x * blockDim.x + threadIdx.x;
    const int per_table = VOCAB * 24;           // 24 groups of 4 channels
    if (idx >= 2 * per_table) return;
    int table = idx / per_table;
    int rem   = idx - table * per_table;
    int p     = rem / 24;
    int c4    = (rem - p * 24) * 4;

    const float4* e4 = reinterpret_cast<const float4*>(emb + p * PEDIM);
    float4 e0 = e4[0], e1 = e4[1], e2 = e4[2], e3 = e4[3];

    float outv[4];
#pragma unroll
    for (int u = 0; u < 4; u++) {
        int c = c4 + u;
        // TH: c<32 -> h2a rows, c>=32 -> a2h rows.  TA: swapped.
        const float* wr = (table == 0)
            ? ((c < 32) ? (h2a_w + c * 32) : (a2h_w + c * 32))
            : ((c < 32) ? (a2h_w + c * 32) : (h2a_w + c * 32));
        const float4* w4 = reinterpret_cast<const float4*>(wr);
        float4 w0 = w4[0], w1 = w4[1], w2 = w4[2], w3 = w4[3];
        float acc = w0.x*e0.x + w0.y*e0.y + w0.z*e0.z + w0.w*e0.w
                  + w1.x*e1.x + w1.y*e1.y + w1.z*e1.z + w1.w*e1.w
                  + w2.x*e2.x + w2.y*e2.y + w2.z*e2.z + w2.w*e2.w
                  + w3.x*e3.x + w3.y*e3.y + w3.z*e3.z + w3.w*e3.w;
        if (c < 32) acc *= RSQRT8;
        outv[u] = acc;
    }
    float* dst = (table == 0) ? g_TH : g_TA;
    *reinterpret_cast<float4*>(dst + p * 96 + c4) =
        make_float4(outv[0], outv[1], outv[2], outv[3]);
}

// Pos tables (bias folded in, q part scaled).
__global__ void build_pos_tables(const float* __restrict__ pos_emb,
                                 const float* __restrict__ h2a_w,
                                 const float* __restrict__ h2a_b,
                                 const float* __restrict__ a2h_w,
                                 const float* __restrict__ a2h_b) {
    int idx = blockIdx.x * blockDim.x + threadIdx.x;
    if (idx >= 2 * NPOS * 96) return;
    int table = idx / (NPOS * 96);
    int rem   = idx - table * (NPOS * 96);
    int pos   = rem / 96;
    int c     = rem - pos * 96;

    const float* wr;
    float bias;
    if (table == 0) { // PH
        if (c < 32) { wr = h2a_w + c * 32; bias = h2a_b[c]; }
        else        { wr = a2h_w + c * 32; bias = a2h_b[c]; }
    } else {          // PA
        if (c < 32) { wr = a2h_w + c * 32; bias = a2h_b[c]; }
        else        { wr = h2a_w + c * 32; bias = h2a_b[c]; }
    }
    float acc = bias;
#pragma unroll
    for (int j = 0; j < PEDIM; j++)
        acc += wr[16 + j] * pos_emb[pos * PEDIM + j];
    if (c < 32) acc *= RSQRT8;
    float* dst = (table == 0) ? g_PH : g_PA;
    dst[pos * 96 + c] = acc;
}

// Fused epilogue weights.
__global__ void build_fused_epilogue(const float* __restrict__ h2a_ow,
                                     const float* __restrict__ h2a_ob,
                                     const float* __restrict__ a2h_ow,
                                     const float* __restrict__ a2h_ob,
                                     const float* __restrict__ gate_w,
                                     const float* __restrict__ gate_b) {
    int tid = blockIdx.x * blockDim.x + threadIdx.x;
    if (tid >= 1024) return;
    int j = tid >> 5;
    int c = tid & 31;
    float wh = h2a_ow[c * 32 + j];
    float wa = a2h_ow[c * 32 + j];
    float gh = 0.f, ga = 0.f;
#pragma unroll
    for (int m = 0; m < 32; m++) {
        gh += gate_w[c * 64 + m]      * h2a_ow[m * 32 + j];
        ga += gate_w[c * 64 + 32 + m] * a2h_ow[m * 32 + j];
    }
    g_wpack[j * 32 + c] = make_float4(wh, wa, gh, ga);
    if (j == 0) {
        float cg = gate_b[c];
#pragma unroll
        for (int m = 0; m < 32; m++) {
            cg += gate_w[c * 64 + m]      * h2a_ob[m];
            cg += gate_w[c * 64 + 32 + m] * a2h_ob[m];
        }
        g_cvec[c] = make_float4(h2a_ob[c], a2h_ob[c], cg, 0.f);
    }
}

// ---------------- main kernel: one warp per batch ----------------
__global__ __launch_bounds__(32 * WPB)
void cross_team_kernel(const int* __restrict__ hpl, const int* __restrict__ apl,
                       const int* __restrict__ hps, const int* __restrict__ aps,
                       const float* __restrict__ lnw, const float* __restrict__ lnb,
                       float* __restrict__ out, int B) {
    __shared__ float sQ[WPB][2][LQ][32];        // per-attn queries (pre-scaled)
    __shared__ float sK[WPB][2][LQ][32];        // per-attn keys
    __shared__ float sS[WPB][2][NHEAD][LQ][12]; // weighted probs (padded stride)
    __shared__ float sAgg[WPB][2][NHEAD][12];   // query-aggregated probs
    __shared__ float sO[WPB][2][32];            // mean attention outputs

    const int w    = threadIdx.x >> 5;
    const int lane = threadIdx.x & 31;
    const int b    = blockIdx.x * WPB + w;
    if (b >= B) return;
    const unsigned FULL = 0xffffffffu;

    // ---- masks ----
    int hp_l = 1, ap_l = 1, hq_l = 0, aq_l = 0;
    if (lane < LQ) {
        hp_l = hpl[b * LQ + lane];
        ap_l = apl[b * LQ + lane];
        hq_l = hps[b * LQ + lane];
        aq_l = aps[b * LQ + lane];
    }
    unsigned hm = __ballot_sync(FULL, (lane < LQ) && (hp_l == 0)) & 0x7FFu;
    unsigned am = __ballot_sync(FULL, (lane < LQ) && (ap_l == 0)) & 0x7FFu;
    unsigned safe_h = (hm == 0x7FFu) ? 0u : hm;   // all-pad rows: mask disabled
    unsigned safe_a = (am == 0x7FFu) ? 0u : am;
    unsigned kpm[2]; kpm[0] = safe_a; kpm[1] = safe_h;         // key padding per attn
    unsigned qv[2];  qv[0] = (~safe_h) & 0x7FFu; qv[1] = (~safe_a) & 0x7FFu;
    float invn[2];
    invn[0] = 1.f / (float)__popc(qv[0]);
    invn[1] = 1.f / (float)__popc(qv[1]);

    // ---- gather q/k/v from fused tables (lane = channel) ----
    float v0r[LQ], v1r[LQ];   // V for attn 0 (away v) and attn 1 (home v)
#pragma unroll
    for (int t = 0; t < LQ; t++) {
        int ph = __shfl_sync(FULL, hp_l, t);
        int pa = __shfl_sync(FULL, ap_l, t);
        int qh = __shfl_sync(FULL, hq_l, t);
        int qa = __shfl_sync(FULL, aq_l, t);
        const float* th = g_TH + ph * 96;
        const float* sh = g_PH + qh * 96;
        const float* ta = g_TA + pa * 96;
        const float* sa = g_PA + qa * 96;
        sQ[w][0][t][lane] = th[lane]      + sh[lane];        // home q (h2a)
        sK[w][1][t][lane] = th[32 + lane] + sh[32 + lane];   // home k (a2h)
        v1r[t]            = th[64 + lane] + sh[64 + lane];   // home v (a2h)
        sQ[w][1][t][lane] = ta[lane]      + sa[lane];        // away q (a2h)
        sK[w][0][t][lane] = ta[32 + lane] + sa[32 + lane];   // away k (h2a)
        v0r[t]            = ta[64 + lane] + sa[64 + lane];   // away v (h2a)
    }
    __syncwarp();

    // ---- fused scores + softmax + query-weighting (lane = (attn,head,query)) ----
#pragma unroll
    for (int it = 0; it < 3; it++) {
        int item = lane + it * 32;
        bool act = item < 88;
        int itc = act ? item : 0;
        int a  = itc / 44;
        int r  = itc - a * 44;
        int h  = r / LQ;
        int qi = r - h * LQ;

        const float* qp = &sQ[w][a][qi][h * 8];
        float4 qA = *reinterpret_cast<const float4*>(qp);
        float4 qB = *reinterpret_cast<const float4*>(qp + 4);
        unsigned kp = kpm[a];

        float s[LQ];
        float mx = -1e30f;
#pragma unroll
        for (int kj = 0; kj < LQ; kj++) {
            const float* kpt = &sK[w][a][kj][h * 8];
            float4 kA = *reinterpret_cast<const float4*>(kpt);
            float4 kB = *reinterpret_cast<const float4*>(kpt + 4);
            float d = qA.x*kA.x + qA.y*kA.y + qA.z*kA.z + qA.w*kA.w
                    + qB.x*kB.x + qB.y*kB.y + qB.z*kB.z + qB.w*kB.w;
            s[kj] = d;
            if (!((kp >> kj) & 1u)) mx = fmaxf(mx, d);
        }
        float sum = 0.f;
#pragma unroll
        for (int kj = 0; kj < LQ; kj++) {
            float e = ((kp >> kj) & 1u) ? 0.f : __expf(s[kj] - mx);
            sum += e;
            s[kj] = e;
        }
        float wq = ((qv[a] >> qi) & 1u) ? (invn[a] / sum) : 0.f;
        if (act) {
#pragma unroll
            for (int kj = 0; kj < LQ; kj++)
                sS[w][a][h][qi][kj] = s[kj] * wq;
        }
    }
    __syncwarp();

    // ---- aggregate probs over queries (lane = (attn,head,key)) ----
#pragma unroll
    for (int it = 0; it < 3; it++) {
        int item = lane + it * 32;
        bool act = item < 88;
        int itc = act ? item : 0;
        int a  = itc / 44;
        int r  = itc - a * 44;
        int h  = r / LQ;
        int kj = r - h * LQ;
        float g = 0.f;
#pragma unroll
        for (int qi = 0; qi < LQ; qi++) g += sS[w][a][h][qi][kj];
        if (act) sAgg[w][a][h][kj] = g;
    }
    __syncwarp();

    // ---- AV with pre-aggregated probs (lane = channel) ----
    {
        int h = lane >> 3;
        float o0 = 0.f, o1 = 0.f;
#pragma unroll
        for (int kj = 0; kj < LQ; kj++) {
            o0 += sAgg[w][0][h][kj] * v0r[kj];
            o1 += sAgg[w][1][h][kj] * v1r[kj];
        }
        sO[w][0][lane] = o0;
        sO[w][1][lane] = o1;
    }
    __syncwarp();

    // ---- fused out_proj + gate + mix + layernorm (lane = channel) ----
    float4 cv = g_cvec[lane];
    float ah = cv.x, aa = cv.y, ag = cv.z;
#pragma unroll
    for (int j = 0; j < 32; j++) {
        float oh = sO[w][0][j];
        float oa = sO[w][1][j];
        float4 wv = g_wpack[j * 32 + lane];
        ah += oh * wv.x;
        aa += oa * wv.y;
        ag += oh * wv.z + oa * wv.w;
    }
    float gate = 1.f / (1.f + __expf(-ag));
    float mch  = gate * ah + (1.f - gate) * aa;

    // layernorm over 32 lanes
    float mu = mch;
#pragma unroll
    for (int off = 16; off > 0; off >>= 1) mu += __shfl_xor_sync(FULL, mu, off);
    mu *= (1.f / 32.f);
    float d = mch - mu;
    float var = d * d;
#pragma unroll
    for (int off = 16; off > 0; off >>= 1) var += __shfl_xor_sync(FULL, var, off);
    var *= (1.f / 32.f);
    float rstd = rsqrtf(var + 1e-5f);
    out[b * 32 + lane] = d * rstd * __ldg(lnw + lane) + __ldg(lnb + lane);
}

// ---------------- launch ----------------
extern "C" void kernel_launch(void* const* d_in, const int* in_sizes, int n_in,
                              void* d_out, int out_size) {
    const int*   hpl     = (const int*)  d_in[0];
    const int*   apl     = (const int*)  d_in[1];
    const int*   hps     = (const int*)  d_in[2];
    const int*   aps     = (const int*)  d_in[3];
    const float* emb     = (const float*)d_in[4];
    const float* pos_emb = (const float*)d_in[5];
    const float* h2a_iw  = (const float*)d_in[6];
    const float* h2a_ib  = (const float*)d_in[7];
    const float* h2a_ow  = (const float*)d_in[8];
    const float* h2a_ob  = (const float*)d_in[9];
    const float* a2h_iw  = (const float*)d_in[10];
    const float* a2h_ib  = (const float*)d_in[11];
    const float* a2h_ow  = (const float*)d_in[12];
    const float* a2h_ob  = (const float*)d_in[13];
    const float* gate_w  = (const float*)d_in[14];
    const float* gate_b  = (const float*)d_in[15];
    const float* lnw     = (const float*)d_in[16];
    const float* lnb     = (const float*)d_in[17];
    float* out = (float*)d_out;

    const int B = in_sizes[0] / LQ;

    build_player_tables<<<(2 * VOCAB * 24 + 255) / 256, 256>>>(emb, h2a_iw, a2h_iw);
    build_pos_tables<<<(2 * NPOS * 96 + 255) / 256, 256>>>(pos_emb, h2a_iw, h2a_ib,
                                                           a2h_iw, a2h_ib);
    build_fused_epilogue<<<4, 256>>>(h2a_ow, h2a_ob, a2h_ow, a2h_ob, gate_w, gate_b);

    cross_team_kernel<<<(B + WPB - 1) / WPB, 32 * WPB>>>(hpl, apl, hps, aps,
                                                         lnw, lnb, out, B);
}